// round 2
// baseline (speedup 1.0000x reference)
#include <cuda_runtime.h>

// LeadLagSignature: depth-3 signature of lead-lag path of 16-point sliding patches.
// dx[2t] = (Delta_t, 0), dx[2t+1] = (0, Delta_t) with Delta_t = patch[t+1]-patch[t].
// One block per output position; thread (a,b) owns S2[a,b] (1 reg) and S3[a,b,0..15] (16 regs).

#define DIM 8
#define PATCH 16
#define NDIFF 15   // diffs per patch
#define LLD 16     // lead-lag dimension

__global__ void __launch_bounds__(256, 6)
leadlag_sig_kernel(const float* __restrict__ x,
                   float* __restrict__ out1,
                   float* __restrict__ out2,
                   float* __restrict__ out3,
                   int seq_len)
{
    __shared__ float sd[NDIFF * DIM];   // Delta_t[c], t in [0,15), c in [0,8)

    const int i   = blockIdx.x;
    const int tid = threadIdx.x;

    // Build the 15 diff vectors of the (zero-left-padded) patch.
    if (tid < NDIFF * DIM) {
        int t = tid >> 3;
        int c = tid & 7;
        int r0 = i + t - (PATCH - 1);       // x-row of patch point t (negative => pad zero)
        int r1 = r0 + 1;
        float p0 = (r0 >= 0) ? x[r0 * DIM + c] : 0.0f;
        float p1 = (r1 >= 0) ? x[r1 * DIM + c] : 0.0f;
        sd[tid] = p1 - p0;
    }
    __syncthreads();

    const int a  = tid >> 4;            // first S3 index / S2 row
    const int b  = tid & 15;            // second S3 index / S2 col
    const int ai = a & 7;
    const int bi = b & 7;
    const bool aLead = (a < 8);
    const bool bLead = (b < 8);

    float s3[LLD];
#pragma unroll
    for (int k = 0; k < LLD; ++k) s3[k] = 0.0f;
    float s2  = 0.0f;   // S2[a,b]
    float s1a = 0.0f;   // S1[a] (replicated across b)

    const float C2 = 0.5f;
    const float C3 = 1.0f / 6.0f;

#pragma unroll
    for (int t = 0; t < NDIFF; ++t) {
        const float4 vlo = *reinterpret_cast<const float4*>(sd + t * 8);
        const float4 vhi = *reinterpret_cast<const float4*>(sd + t * 8 + 4);
        const float va = sd[t * 8 + ai];
        const float vb = sd[t * 8 + bi];

        // ---- increment 2t: lead half (columns 0..7) ----
        {
            const float pa = aLead ? va : 0.0f;
            const float pb = bLead ? vb : 0.0f;
            const float g  = s1a * pb;          // S1[a]*dx[b]
            const float pp = pa * pb;           // dx[a]*dx[b]
            const float F  = s2 + C2 * g + C3 * pp;
            s3[0] = fmaf(F, vlo.x, s3[0]);
            s3[1] = fmaf(F, vlo.y, s3[1]);
            s3[2] = fmaf(F, vlo.z, s3[2]);
            s3[3] = fmaf(F, vlo.w, s3[3]);
            s3[4] = fmaf(F, vhi.x, s3[4]);
            s3[5] = fmaf(F, vhi.y, s3[5]);
            s3[6] = fmaf(F, vhi.z, s3[6]);
            s3[7] = fmaf(F, vhi.w, s3[7]);
            s2  = s2 + g + C2 * pp;
            s1a = s1a + pa;
        }
        // ---- increment 2t+1: lag half (columns 8..15) ----
        {
            const float pa = aLead ? 0.0f : va;
            const float pb = bLead ? 0.0f : vb;
            const float g  = s1a * pb;
            const float pp = pa * pb;
            const float F  = s2 + C2 * g + C3 * pp;
            s3[8]  = fmaf(F, vlo.x, s3[8]);
            s3[9]  = fmaf(F, vlo.y, s3[9]);
            s3[10] = fmaf(F, vlo.z, s3[10]);
            s3[11] = fmaf(F, vlo.w, s3[11]);
            s3[12] = fmaf(F, vhi.x, s3[12]);
            s3[13] = fmaf(F, vhi.y, s3[13]);
            s3[14] = fmaf(F, vhi.z, s3[14]);
            s3[15] = fmaf(F, vhi.w, s3[15]);
            s2  = s2 + g + C2 * pp;
            s1a = s1a + pa;
        }
    }

    // ---- write outputs ----
    if (b == 0) out1[i * LLD + a] = s1a;                 // level 1: [seq, 16]
    out2[i * (LLD * LLD) + tid] = s2;                    // level 2: [seq, 16, 16]

    float4* o3 = reinterpret_cast<float4*>(out3 + (size_t)i * (LLD * LLD * LLD) + tid * LLD);
    o3[0] = make_float4(s3[0],  s3[1],  s3[2],  s3[3]);
    o3[1] = make_float4(s3[4],  s3[5],  s3[6],  s3[7]);
    o3[2] = make_float4(s3[8],  s3[9],  s3[10], s3[11]);
    o3[3] = make_float4(s3[12], s3[13], s3[14], s3[15]);
}

extern "C" void kernel_launch(void* const* d_in, const int* in_sizes, int n_in,
                              void* d_out, int out_size)
{
    const float* x = (const float*)d_in[0];
    const int seq_len = in_sizes[0] / DIM;

    float* out = (float*)d_out;
    float* out1 = out;
    float* out2 = out + (size_t)seq_len * LLD;
    float* out3 = out + (size_t)seq_len * LLD + (size_t)seq_len * LLD * LLD;

    leadlag_sig_kernel<<<seq_len, 256>>>(x, out1, out2, out3, seq_len);
}

// round 3
// speedup vs baseline: 1.1454x; 1.1454x over previous
#include <cuda_runtime.h>

// LeadLagSignature depth-3, lead-lag of 16-point sliding patches.
// dx[2t] = (Delta_t, 0), dx[2t+1] = (0, Delta_t), Delta_t = patch[t+1]-patch[t].
// One block per position; thread (a,b) owns S2[a,b] and S3[a,b,0..15].
// R2: f32x2 packed FFMA for the S3 rank-1 updates + warp-uniform aLead specialization.

#define DIM 8
#define PATCH 16
#define NDIFF 15
#define LLD 16

__device__ __forceinline__ unsigned long long ffma2(unsigned long long a,
                                                    unsigned long long b,
                                                    unsigned long long c) {
    unsigned long long d;
    asm("fma.rn.f32x2 %0, %1, %2, %3;" : "=l"(d) : "l"(a), "l"(b), "l"(c));
    return d;
}

__device__ __forceinline__ unsigned long long bcast2(float f) {
    unsigned int r = __float_as_uint(f);
    unsigned long long d;
    asm("mov.b64 %0, {%1, %1};" : "=l"(d) : "r"(r));
    return d;
}

// ALEAD: whether index a is in the lead half (warp-uniform).
template <bool ALEAD>
__device__ __forceinline__ void sig_loop(const float* __restrict__ sd,
                                         int ai, int bi, bool bLead,
                                         unsigned long long* s3p,
                                         float& s2, float& s1a) {
    const float C2 = 0.5f;
    const float C3 = 1.0f / 6.0f;
#pragma unroll
    for (int t = 0; t < NDIFF; ++t) {
        // v[0..7] as four packed f32x2 pairs (two LDS.128)
        const ulonglong2 pA = *reinterpret_cast<const ulonglong2*>(sd + t * 8);
        const ulonglong2 pB = *reinterpret_cast<const ulonglong2*>(sd + t * 8 + 4);
        const float va = sd[t * 8 + ai];
        const float vb = sd[t * 8 + bi];
        const float pbl = bLead ? vb : 0.0f;   // b-component of lead increment
        const float pbg = bLead ? 0.0f : vb;   // b-component of lag increment

        float F, F2;
        if (ALEAD) {
            // lead step: pa = va, pb = pbl
            const float u = fmaf(C3, va, C2 * s1a);
            F  = fmaf(pbl, u, s2);
            const float w = fmaf(C2, va, s1a);
            s2 = fmaf(pbl, w, s2);
            s1a += va;
            // lag step: pa = 0, pb = pbg (uses updated s1a, s2)
            F2 = fmaf(pbg, C2 * s1a, s2);
            s2 = fmaf(pbg, s1a, s2);
        } else {
            // lead step: pa = 0, pb = pbl
            F  = fmaf(pbl, C2 * s1a, s2);
            s2 = fmaf(pbl, s1a, s2);
            // lag step: pa = va, pb = pbg
            const float u = fmaf(C3, va, C2 * s1a);
            F2 = fmaf(pbg, u, s2);
            const float w = fmaf(C2, va, s1a);
            s2 = fmaf(pbg, w, s2);
            s1a += va;
        }

        const unsigned long long Fp  = bcast2(F);
        const unsigned long long F2p = bcast2(F2);
        // S3[a,b,0..7] += F * v   (lead columns)
        s3p[0] = ffma2(Fp, pA.x, s3p[0]);
        s3p[1] = ffma2(Fp, pA.y, s3p[1]);
        s3p[2] = ffma2(Fp, pB.x, s3p[2]);
        s3p[3] = ffma2(Fp, pB.y, s3p[3]);
        // S3[a,b,8..15] += F2 * v (lag columns)
        s3p[4] = ffma2(F2p, pA.x, s3p[4]);
        s3p[5] = ffma2(F2p, pA.y, s3p[5]);
        s3p[6] = ffma2(F2p, pB.x, s3p[6]);
        s3p[7] = ffma2(F2p, pB.y, s3p[7]);
    }
}

__global__ void __launch_bounds__(256, 6)
leadlag_sig_kernel(const float* __restrict__ x,
                   float* __restrict__ out1,
                   float* __restrict__ out2,
                   float* __restrict__ out3,
                   int seq_len)
{
    __shared__ __align__(16) float sd[NDIFF * DIM];

    const int i   = blockIdx.x;
    const int tid = threadIdx.x;

    if (tid < NDIFF * DIM) {
        int t = tid >> 3;
        int c = tid & 7;
        int r0 = i + t - (PATCH - 1);
        int r1 = r0 + 1;
        float p0 = (r0 >= 0) ? x[r0 * DIM + c] : 0.0f;
        float p1 = (r1 >= 0) ? x[r1 * DIM + c] : 0.0f;
        sd[tid] = p1 - p0;
    }
    __syncthreads();

    const int a  = tid >> 4;
    const int b  = tid & 15;
    const int ai = a & 7;
    const int bi = b & 7;
    const bool bLead = (b < 8);

    unsigned long long s3p[8];
#pragma unroll
    for (int k = 0; k < 8; ++k) s3p[k] = 0ULL;
    float s2  = 0.0f;
    float s1a = 0.0f;

    if (a < 8) {   // warp-uniform branch
        sig_loop<true>(sd, ai, bi, bLead, s3p, s2, s1a);
    } else {
        sig_loop<false>(sd, ai, bi, bLead, s3p, s2, s1a);
    }

    // ---- outputs ----
    if (b == 0) out1[i * LLD + a] = s1a;
    out2[i * (LLD * LLD) + tid] = s2;

    ulonglong2* o3 = reinterpret_cast<ulonglong2*>(
        out3 + (size_t)i * (LLD * LLD * LLD) + tid * LLD);
    o3[0] = make_ulonglong2(s3p[0], s3p[1]);
    o3[1] = make_ulonglong2(s3p[2], s3p[3]);
    o3[2] = make_ulonglong2(s3p[4], s3p[5]);
    o3[3] = make_ulonglong2(s3p[6], s3p[7]);
}

extern "C" void kernel_launch(void* const* d_in, const int* in_sizes, int n_in,
                              void* d_out, int out_size)
{
    const float* x = (const float*)d_in[0];
    const int seq_len = in_sizes[0] / DIM;

    float* out = (float*)d_out;
    float* out1 = out;
    float* out2 = out + (size_t)seq_len * LLD;
    float* out3 = out + (size_t)seq_len * LLD + (size_t)seq_len * LLD * LLD;

    leadlag_sig_kernel<<<seq_len, 256>>>(x, out1, out2, out3, seq_len);
}

// round 4
// speedup vs baseline: 1.3839x; 1.2082x over previous
#include <cuda_runtime.h>

// LeadLagSignature depth-3, lead-lag of 16-point sliding patches.
// R3: each thread owns TWO output columns (b, b+8) — same bi, lead+lag pair —
// halving LDS traffic per unit of S3 work. 128 threads/block.

#define DIM 8
#define PATCH 16
#define NDIFF 15
#define LLD 16

__device__ __forceinline__ unsigned long long ffma2(unsigned long long a,
                                                    unsigned long long b,
                                                    unsigned long long c) {
    unsigned long long d;
    asm("fma.rn.f32x2 %0, %1, %2, %3;" : "=l"(d) : "l"(a), "l"(b), "l"(c));
    return d;
}

__device__ __forceinline__ unsigned long long bcast2(float f) {
    unsigned int r = __float_as_uint(f);
    unsigned long long d;
    asm("mov.b64 %0, {%1, %1};" : "=l"(d) : "r"(r));
    return d;
}

// ALEAD: whether row index a is in the lead half (warp-uniform: a = tid>>3
// spans 4 consecutive values per warp, all on one side of 8).
template <bool ALEAD>
__device__ __forceinline__ void sig_loop(const float* __restrict__ sd,
                                         int ai, int bi,
                                         unsigned long long* s3b,   // column b   (lead), 8 u64
                                         unsigned long long* s3g,   // column b+8 (lag),  8 u64
                                         float& s2b, float& s2g, float& s1a) {
    const float C2 = 0.5f;
    const float C3 = 1.0f / 6.0f;
#pragma unroll
    for (int t = 0; t < NDIFF; ++t) {
        const ulonglong2 pA = *reinterpret_cast<const ulonglong2*>(sd + t * 8);
        const ulonglong2 pB = *reinterpret_cast<const ulonglong2*>(sd + t * 8 + 4);
        const float va = sd[t * 8 + ai];
        const float vb = sd[t * 8 + bi];

        float Fb, F2b, Fg, F2g;
        if (ALEAD) {
            // lead step: pa=va; pb: col b -> vb, col b+8 -> 0
            Fg = s2g;                                 // pb=0
            const float cs1 = C2 * s1a;
            const float u   = fmaf(C3, va, cs1);
            Fb  = fmaf(vb, u, s2b);
            const float w   = fmaf(C2, va, s1a);
            s2b = fmaf(vb, w, s2b);
            s1a += va;
            // lag step: pa=0; pb: col b -> 0, col b+8 -> vb
            F2b = s2b;                                // pb=0
            const float h   = C2 * s1a;
            F2g = fmaf(vb, h, s2g);
            s2g = fmaf(vb, s1a, s2g);
        } else {
            // lead step: pa=0; pb: col b -> vb, col b+8 -> 0
            const float cs1 = C2 * s1a;
            Fb  = fmaf(vb, cs1, s2b);
            s2b = fmaf(vb, s1a, s2b);
            Fg  = s2g;
            // lag step: pa=va; pb: col b -> 0, col b+8 -> vb
            F2b = s2b;
            const float u   = fmaf(C3, va, cs1);
            F2g = fmaf(vb, u, s2g);
            const float w   = fmaf(C2, va, s1a);
            s2g = fmaf(vb, w, s2g);
            s1a += va;
        }

        const unsigned long long Fbp  = bcast2(Fb);
        const unsigned long long F2bp = bcast2(F2b);
        const unsigned long long Fgp  = bcast2(Fg);
        const unsigned long long F2gp = bcast2(F2g);

        // column b: S3[a,b,0..7] += Fb*v, S3[a,b,8..15] += F2b*v
        s3b[0] = ffma2(Fbp,  pA.x, s3b[0]);
        s3b[1] = ffma2(Fbp,  pA.y, s3b[1]);
        s3b[2] = ffma2(Fbp,  pB.x, s3b[2]);
        s3b[3] = ffma2(Fbp,  pB.y, s3b[3]);
        s3b[4] = ffma2(F2bp, pA.x, s3b[4]);
        s3b[5] = ffma2(F2bp, pA.y, s3b[5]);
        s3b[6] = ffma2(F2bp, pB.x, s3b[6]);
        s3b[7] = ffma2(F2bp, pB.y, s3b[7]);
        // column b+8
        s3g[0] = ffma2(Fgp,  pA.x, s3g[0]);
        s3g[1] = ffma2(Fgp,  pA.y, s3g[1]);
        s3g[2] = ffma2(Fgp,  pB.x, s3g[2]);
        s3g[3] = ffma2(Fgp,  pB.y, s3g[3]);
        s3g[4] = ffma2(F2gp, pA.x, s3g[4]);
        s3g[5] = ffma2(F2gp, pA.y, s3g[5]);
        s3g[6] = ffma2(F2gp, pB.x, s3g[6]);
        s3g[7] = ffma2(F2gp, pB.y, s3g[7]);
    }
}

__global__ void __launch_bounds__(128, 6)
leadlag_sig_kernel(const float* __restrict__ x,
                   float* __restrict__ out1,
                   float* __restrict__ out2,
                   float* __restrict__ out3,
                   int seq_len)
{
    __shared__ __align__(16) float sd[NDIFF * DIM];

    const int i   = blockIdx.x;
    const int tid = threadIdx.x;

    if (tid < NDIFF * DIM) {
        int t = tid >> 3;
        int c = tid & 7;
        int r0 = i + t - (PATCH - 1);
        int r1 = r0 + 1;
        float p0 = (r0 >= 0) ? x[r0 * DIM + c] : 0.0f;
        float p1 = (r1 >= 0) ? x[r1 * DIM + c] : 0.0f;
        sd[tid] = p1 - p0;
    }
    __syncthreads();

    const int a  = tid >> 3;        // 0..15
    const int b  = tid & 7;         // lead column; lag column is b+8
    const int ai = a & 7;

    unsigned long long s3b[8], s3g[8];
#pragma unroll
    for (int k = 0; k < 8; ++k) { s3b[k] = 0ULL; s3g[k] = 0ULL; }
    float s2b = 0.0f, s2g = 0.0f, s1a = 0.0f;

    if (a < 8) {   // warp-uniform
        sig_loop<true >(sd, ai, b, s3b, s3g, s2b, s2g, s1a);
    } else {
        sig_loop<false>(sd, ai, b, s3b, s3g, s2b, s2g, s1a);
    }

    // ---- outputs ----
    if (b == 0) out1[i * LLD + a] = s1a;
    const int r2 = i * (LLD * LLD) + a * LLD + b;
    out2[r2]     = s2b;
    out2[r2 + 8] = s2g;

    float* base = out3 + (size_t)i * (LLD * LLD * LLD);
    ulonglong2* ob = reinterpret_cast<ulonglong2*>(base + (a * LLD + b) * LLD);
    ob[0] = make_ulonglong2(s3b[0], s3b[1]);
    ob[1] = make_ulonglong2(s3b[2], s3b[3]);
    ob[2] = make_ulonglong2(s3b[4], s3b[5]);
    ob[3] = make_ulonglong2(s3b[6], s3b[7]);
    ulonglong2* og = reinterpret_cast<ulonglong2*>(base + (a * LLD + b + 8) * LLD);
    og[0] = make_ulonglong2(s3g[0], s3g[1]);
    og[1] = make_ulonglong2(s3g[2], s3g[3]);
    og[2] = make_ulonglong2(s3g[4], s3g[5]);
    og[3] = make_ulonglong2(s3g[6], s3g[7]);
}

extern "C" void kernel_launch(void* const* d_in, const int* in_sizes, int n_in,
                              void* d_out, int out_size)
{
    const float* x = (const float*)d_in[0];
    const int seq_len = in_sizes[0] / DIM;

    float* out = (float*)d_out;
    float* out1 = out;
    float* out2 = out + (size_t)seq_len * LLD;
    float* out3 = out + (size_t)seq_len * LLD + (size_t)seq_len * LLD * LLD;

    leadlag_sig_kernel<<<seq_len, 128>>>(x, out1, out2, out3, seq_len);
}